// round 11
// baseline (speedup 1.0000x reference)
#include <cuda_runtime.h>
#include <cuda_fp16.h>
#include <cstdint>
#include <math.h>

#define BB 16
#define CC 512
#define LL 1024
#define GG 32
#define CPG 16
#define HEADS 8
#define CHH 64

// Scratch (no allocation allowed)
__device__ __half g_hT[BB * LL * CC];                 // h transposed [b][l][c], fp16
__device__ __half g_wh[3 * CC * CC];                  // conv weight fp16
__device__ __half g_qkT[BB * 2 * HEADS * LL * CHH];   // q,k transposed; q pre-scaled by 0.125*log2(e)
__device__ __half g_v[BB * CC * LL];                  // v natural [b][ch_global][l]

__device__ __forceinline__ void mma_f16(float d[4], const unsigned a[4], const unsigned b[2]) {
    asm volatile(
        "mma.sync.aligned.m16n8k16.row.col.f32.f16.f16.f32 "
        "{%0,%1,%2,%3}, {%4,%5,%6,%7}, {%8,%9}, {%0,%1,%2,%3};"
        : "+f"(d[0]), "+f"(d[1]), "+f"(d[2]), "+f"(d[3])
        : "r"(a[0]), "r"(a[1]), "r"(a[2]), "r"(a[3]),
          "r"(b[0]), "r"(b[1]));
}

__device__ __forceinline__ void ldsm4(unsigned r[4], unsigned saddr) {
    asm volatile("ldmatrix.sync.aligned.m8n8.x4.shared.b16 {%0,%1,%2,%3}, [%4];"
                 : "=r"(r[0]), "=r"(r[1]), "=r"(r[2]), "=r"(r[3]) : "r"(saddr));
}

__device__ __forceinline__ unsigned ex2_f16x2(unsigned v) {
    unsigned r;
    asm("ex2.approx.f16x2 %0, %1;" : "=r"(r) : "r"(v));
    return r;
}

__device__ __forceinline__ void cp16h(__half* dst_smem, const __half* src) {
    unsigned d = (unsigned)__cvta_generic_to_shared(dst_smem);
    asm volatile("cp.async.cg.shared.global [%0], [%1], 16;" :: "r"(d), "l"(src));
}
__device__ __forceinline__ void cp_commit() { asm volatile("cp.async.commit_group;"); }
__device__ __forceinline__ void cp_wait1() { asm volatile("cp.async.wait_group 1;"); }
__device__ __forceinline__ void cp_wait2() { asm volatile("cp.async.wait_group 2;"); }

// ---------------------------------------------------------------------------
// Kernel 0: convert conv weight to fp16.
// ---------------------------------------------------------------------------
__global__ void wconv_kernel(const float* __restrict__ W) {
    int i = blockIdx.x * 256 + threadIdx.x;
    float2 w = ((const float2*)W)[i];
    ((__half2*)g_wh)[i] = __floats2half2_rn(w.x, w.y);
}

// ---------------------------------------------------------------------------
// Kernel 1: GroupNorm(32) -> hT [b][l][c] fp16. One block per (b, g).
// ---------------------------------------------------------------------------
__global__ void gn_kernel(const float* __restrict__ x,
                          const float* __restrict__ gw,
                          const float* __restrict__ gb) {
    int bg = blockIdx.x;
    int b = bg >> 5, g = bg & 31;
    const float* xp = x + ((size_t)b * CC + (size_t)g * CPG) * LL;
    const float4* xp4 = (const float4*)xp;
    int t = threadIdx.x;

    float s = 0.f, ss = 0.f;
    for (int i = t; i < CPG * LL / 4; i += 256) {
        float4 v = xp4[i];
        s += v.x + v.y + v.z + v.w;
        ss += v.x * v.x + v.y * v.y + v.z * v.z + v.w * v.w;
    }
    __shared__ float r0[256], r1[256];
    r0[t] = s; r1[t] = ss;
    __syncthreads();
    for (int o = 128; o > 0; o >>= 1) {
        if (t < o) { r0[t] += r0[t + o]; r1[t] += r1[t + o]; }
        __syncthreads();
    }
    const float invN = 1.f / (CPG * LL);
    float mean = r0[0] * invN;
    float var = r1[0] * invN - mean * mean;
    float rstd = rsqrtf(var + 1e-5f);

    int h = t & 1;
    float wv[8], bv[8];
#pragma unroll
    for (int j = 0; j < 8; j++) {
        int cg = g * CPG + h * 8 + j;
        wv[j] = gw[cg] * rstd;
        bv[j] = gb[cg] - mean * wv[j];
    }

    for (int u = t; u < 2 * LL; u += 256) {
        int l = u >> 1;
        uint4 pack;
        __half2* ph = (__half2*)&pack;
#pragma unroll
        for (int j = 0; j < 4; j++) {
            float v0 = xp[(size_t)(h * 8 + 2 * j) * LL + l];
            float v1 = xp[(size_t)(h * 8 + 2 * j + 1) * LL + l];
            ph[j] = __floats2half2_rn(v0 * wv[2 * j] + bv[2 * j],
                                      v1 * wv[2 * j + 1] + bv[2 * j + 1]);
        }
        *(uint4*)(g_hT + ((size_t)b * LL + l) * CC + g * CPG + h * 8) = pack;
    }
}

// ---------------------------------------------------------------------------
// Kernel 2: unified QKV GEMM, 128x128 block tiles, K-chunk 64, 8 warps.
// ---------------------------------------------------------------------------
#define GP 72
#define GSMEM (4 * 128 * GP * 2)

__global__ void __launch_bounds__(256, 2) qkv_gemm(const float* __restrict__ bias) {
    extern __shared__ __half dyn[];
    __half* As[2] = {dyn, dyn + 128 * GP};
    __half* Bs[2] = {dyn + 2 * 128 * GP, dyn + 3 * 128 * GP};

    int id = blockIdx.x;
    bool isqk = id < 1024;
    int b, o0, l0;
    const __half *Asrc, *Bsrc;
    if (isqk) {
        int r = id & 63;
        b = id >> 6;
        l0 = (r & 7) * 128; o0 = (r >> 3) * 128;
        Asrc = g_hT + ((size_t)b * LL + l0) * CC;
        Bsrc = g_wh + (size_t)o0 * CC;
    } else {
        int id2 = id - 1024;
        int r = id2 & 31;
        b = id2 >> 5;
        l0 = (r & 7) * 128; o0 = (r >> 3) * 128;
        Asrc = g_wh + (size_t)(2 * CC + o0) * CC;
        Bsrc = g_hT + ((size_t)b * LL + l0) * CC;
    }
    int t = threadIdx.x, warp = t >> 5, lane = t & 31;
    int g = lane >> 2, tt = lane & 3;
    int wm = warp >> 2, wn = warp & 3;

    int sr = t >> 3, sc = (t & 7) * 8;

    int arow = (lane & 7) + 8 * ((lane >> 3) & 1);
    int acol = 8 * (lane >> 4);
    int brow = (lane & 7) + 8 * ((lane >> 4) & 1);
    int bcol = 8 * ((lane >> 3) & 1);
    unsigned aoff = (unsigned)((wm * 64 + arow) * GP + acol) * 2;
    unsigned boff = (unsigned)((wn * 32 + brow) * GP + bcol) * 2;
    unsigned sA[2] = {(unsigned)__cvta_generic_to_shared(As[0]) + aoff,
                      (unsigned)__cvta_generic_to_shared(As[1]) + aoff};
    unsigned sB[2] = {(unsigned)__cvta_generic_to_shared(Bs[0]) + boff,
                      (unsigned)__cvta_generic_to_shared(Bs[1]) + boff};

    float acc[4][4][4];
#pragma unroll
    for (int m = 0; m < 4; m++)
#pragma unroll
        for (int n = 0; n < 4; n++)
#pragma unroll
            for (int r = 0; r < 4; r++) acc[m][n][r] = 0.f;

#pragma unroll
    for (int i = 0; i < 4; i++) {
        int rw = sr + i * 32;
        cp16h(&As[0][rw * GP + sc], Asrc + (size_t)rw * CC + sc);
        cp16h(&Bs[0][rw * GP + sc], Bsrc + (size_t)rw * CC + sc);
    }
    cp_commit();

    for (int ic = 0; ic < 8; ic++) {
        int cur = ic & 1;
        if (ic + 1 < 8) {
            int nxt = cur ^ 1, c0 = (ic + 1) * 64;
#pragma unroll
            for (int i = 0; i < 4; i++) {
                int rw = sr + i * 32;
                cp16h(&As[nxt][rw * GP + sc], Asrc + (size_t)rw * CC + c0 + sc);
                cp16h(&Bs[nxt][rw * GP + sc], Bsrc + (size_t)rw * CC + c0 + sc);
            }
            cp_commit();
            cp_wait1();
        } else {
            asm volatile("cp.async.wait_group 0;");
        }
        __syncthreads();

#pragma unroll
        for (int kk = 0; kk < 4; kk++) {
            unsigned a[4][4], bb[2][4];
#pragma unroll
            for (int mm = 0; mm < 4; mm++)
                ldsm4(a[mm], sA[cur] + (unsigned)(mm * 16 * GP + kk * 16) * 2);
#pragma unroll
            for (int i = 0; i < 2; i++)
                ldsm4(bb[i], sB[cur] + (unsigned)(i * 16 * GP + kk * 16) * 2);
#pragma unroll
            for (int mm = 0; mm < 4; mm++)
#pragma unroll
                for (int nn = 0; nn < 4; nn++) {
                    unsigned bf[2] = {bb[nn >> 1][2 * (nn & 1)],
                                      bb[nn >> 1][2 * (nn & 1) + 1]};
                    mma_f16(acc[mm][nn], a[mm], bf);
                }
        }
        __syncthreads();
    }

    const float QSC = 0.125f * 1.4426950408889634f;
    if (isqk) {
#pragma unroll
        for (int mm = 0; mm < 4; mm++) {
            int l = l0 + wm * 64 + mm * 16 + g;
#pragma unroll
            for (int nn = 0; nn < 4; nn++) {
                int o = o0 + wn * 32 + nn * 8 + 2 * tt;
                int sec = o >> 9, head = (o >> 6) & 7, ch = o & 63;
                float sc2 = (sec == 0) ? QSC : 1.f;
                __half* dst = g_qkT + (((size_t)b * 2 + sec) * 8 + head) * LL * CHH;
                float2 b2 = *(const float2*)&bias[o];
                *(__half2*)&dst[(size_t)l * CHH + ch] =
                    __floats2half2_rn((acc[mm][nn][0] + b2.x) * sc2, (acc[mm][nn][1] + b2.y) * sc2);
                *(__half2*)&dst[(size_t)(l + 8) * CHH + ch] =
                    __floats2half2_rn((acc[mm][nn][2] + b2.x) * sc2, (acc[mm][nn][3] + b2.y) * sc2);
            }
        }
    } else {
        __half* dst = g_v + (size_t)b * CC * LL;
#pragma unroll
        for (int mm = 0; mm < 4; mm++) {
            int o = o0 + wm * 64 + mm * 16 + g;
            float b0 = bias[2 * CC + o], b1 = bias[2 * CC + o + 8];
#pragma unroll
            for (int nn = 0; nn < 4; nn++) {
                int l = l0 + wn * 32 + nn * 8 + 2 * tt;
                *(__half2*)&dst[(size_t)o * LL + l] =
                    __floats2half2_rn(acc[mm][nn][0] + b0, acc[mm][nn][1] + b0);
                *(__half2*)&dst[(size_t)(o + 8) * LL + l] =
                    __floats2half2_rn(acc[mm][nn][2] + b1, acc[mm][nn][3] + b1);
            }
        }
    }
}

// ---------------------------------------------------------------------------
// Kernel 3: flash attention, software-pipelined: S[ic+1] HMMAs issued before
// softmax(S[ic]) so the tensor pipe stays busy through the softmax chain.
// 3-stage K ring, 2-stage V ring, one commit per iteration.
// ---------------------------------------------------------------------------
#define FPAD 72
#define TILE_B (64 * FPAD * 2)
#define FSMEM (6 * TILE_B)          // Q + 3K + 2V
#define AS_ST 68

__global__ void __launch_bounds__(128, 3) attn_flash(const float* __restrict__ x,
                                                     float* __restrict__ out) {
    extern __shared__ char smc[];
    __half* Qs = (__half*)smc;
    __half* Kb[3] = {(__half*)(smc + TILE_B), (__half*)(smc + 2 * TILE_B),
                     (__half*)(smc + 3 * TILE_B)};
    __half* Vb[2] = {(__half*)(smc + 4 * TILE_B), (__half*)(smc + 5 * TILE_B)};

    int q0 = blockIdx.x;                 // 0..15 (64 queries each)
    int bh = blockIdx.y;                 // 0..127
    int b = bh >> 3, head = bh & 7;
    int t = threadIdx.x, warp = t >> 5, lane = t & 31;
    int g = lane >> 2, tt = lane & 3;

    const __half* qbase = g_qkT + (((size_t)b * 2 + 0) * 8 + head) * LL * CHH;
    const __half* kbase = g_qkT + (((size_t)b * 2 + 1) * 8 + head) * LL * CHH;
    const __half* vbase = g_v + ((size_t)b * CC + head * CHH) * LL;

    int sr = t >> 3, sc = (t & 7) * 8;

    int brow = (lane & 7) + 8 * ((lane >> 4) & 1);
    int bcol = 8 * ((lane >> 3) & 1);
    unsigned kvoff = (unsigned)(brow * FPAD + bcol) * 2;
    unsigned sK[3] = {(unsigned)__cvta_generic_to_shared(Kb[0]) + kvoff,
                      (unsigned)__cvta_generic_to_shared(Kb[1]) + kvoff,
                      (unsigned)__cvta_generic_to_shared(Kb[2]) + kvoff};
    unsigned sV[2] = {(unsigned)__cvta_generic_to_shared(Vb[0]) + kvoff,
                      (unsigned)__cvta_generic_to_shared(Vb[1]) + kvoff};

    // prologue: g0 = {Q, K0, V0}; g1 = {K1}; g2 = {K2, V1}
#pragma unroll
    for (int i = 0; i < 4; i++) {
        int rw = sr + i * 16;
        cp16h(&Qs[rw * FPAD + sc], qbase + (size_t)(q0 * 64 + rw) * CHH + sc);
        cp16h(&Kb[0][rw * FPAD + sc], kbase + (size_t)rw * CHH + sc);
        cp16h(&Vb[0][rw * FPAD + sc], vbase + (size_t)rw * LL + sc);
    }
    cp_commit();
#pragma unroll
    for (int i = 0; i < 4; i++) {
        int rw = sr + i * 16;
        cp16h(&Kb[1][rw * FPAD + sc], kbase + (size_t)(64 + rw) * CHH + sc);
    }
    cp_commit();
#pragma unroll
    for (int i = 0; i < 4; i++) {
        int rw = sr + i * 16;
        cp16h(&Kb[2][rw * FPAD + sc], kbase + (size_t)(128 + rw) * CHH + sc);
        cp16h(&Vb[1][rw * FPAD + sc], vbase + (size_t)rw * LL + 64 + sc);
    }
    cp_commit();

    float m0 = -INFINITY, m1 = -INFINITY;
    float l0 = 0.f, l1 = 0.f;
    float o[8][4];
#pragma unroll
    for (int j = 0; j < 8; j++)
#pragma unroll
        for (int r = 0; r < 4; r++) o[j][r] = 0.f;

    // pre-loop: Q fragments + S[0]
    cp_wait2();            // g0 complete: Q, K0, V0
    __syncthreads();

    unsigned qa[4][4];
    {
        const __half* qp = &Qs[(warp * 16 + g) * FPAD];
#pragma unroll
        for (int kk = 0; kk < 4; kk++) {
            const __half* p = qp + kk * 16 + 2 * tt;
            qa[kk][0] = *(const unsigned*)p;
            qa[kk][1] = *(const unsigned*)(p + 8 * FPAD);
            qa[kk][2] = *(const unsigned*)(p + 8);
            qa[kk][3] = *(const unsigned*)(p + 8 * FPAD + 8);
        }
    }

    float d[8][4];
#pragma unroll
    for (int j = 0; j < 8; j++)
        d[j][0] = d[j][1] = d[j][2] = d[j][3] = 0.f;
#pragma unroll
    for (int kk = 0; kk < 4; kk++)
#pragma unroll
        for (int i = 0; i < 4; i++) {
            unsigned r[4];
            ldsm4(r, sK[0] + (unsigned)(i * 16 * FPAD + kk * 16) * 2);
            unsigned blo[2] = {r[0], r[1]}, bhi[2] = {r[2], r[3]};
            mma_f16(d[2 * i], qa[kk], blo);
            mma_f16(d[2 * i + 1], qa[kk], bhi);
        }

    for (int ic = 0; ic < 16; ic++) {
        cp_wait1();        // completes g(ic+1): K[ic+1], V[ic]
        __syncthreads();

        // ---- S[ic+1] first: independent HMMA stream to hide softmax chain ----
        float dn[8][4];
        if (ic < 15) {
            unsigned K = sK[(ic + 1) % 3];
#pragma unroll
            for (int j = 0; j < 8; j++)
                dn[j][0] = dn[j][1] = dn[j][2] = dn[j][3] = 0.f;
#pragma unroll
            for (int kk = 0; kk < 4; kk++)
#pragma unroll
                for (int i = 0; i < 4; i++) {
                    unsigned r[4];
                    ldsm4(r, K + (unsigned)(i * 16 * FPAD + kk * 16) * 2);
                    unsigned blo[2] = {r[0], r[1]}, bhi[2] = {r[2], r[3]};
                    mma_f16(dn[2 * i], qa[kk], blo);
                    mma_f16(dn[2 * i + 1], qa[kk], bhi);
                }
        }

        // ---- online softmax on S[ic] (exp2 domain, f16x2 MUFU) ----
        float cm0 = -INFINITY, cm1 = -INFINITY;
#pragma unroll
        for (int j = 0; j < 8; j++) {
            cm0 = fmaxf(cm0, fmaxf(d[j][0], d[j][1]));
            cm1 = fmaxf(cm1, fmaxf(d[j][2], d[j][3]));
        }
        cm0 = fmaxf(cm0, __shfl_xor_sync(0xffffffffu, cm0, 1));
        cm0 = fmaxf(cm0, __shfl_xor_sync(0xffffffffu, cm0, 2));
        cm1 = fmaxf(cm1, __shfl_xor_sync(0xffffffffu, cm1, 1));
        cm1 = fmaxf(cm1, __shfl_xor_sync(0xffffffffu, cm1, 2));

        float mn0 = fmaxf(m0, cm0), mn1 = fmaxf(m1, cm1);
        float al0 = exp2f(m0 - mn0), al1 = exp2f(m1 - mn1);
        m0 = mn0; m1 = mn1;

        float rs0 = 0.f, rs1 = 0.f;
        unsigned p2[8][2];
#pragma unroll
        for (int j = 0; j < 8; j++) {
            __half2 s01 = __floats2half2_rn(d[j][0] - m0, d[j][1] - m0);
            __half2 s23 = __floats2half2_rn(d[j][2] - m1, d[j][3] - m1);
            p2[j][0] = ex2_f16x2(*(unsigned*)&s01);
            p2[j][1] = ex2_f16x2(*(unsigned*)&s23);
            float2 f01 = __half22float2(*(__half2*)&p2[j][0]);
            float2 f23 = __half22float2(*(__half2*)&p2[j][1]);
            rs0 += f01.x + f01.y;
            rs1 += f23.x + f23.y;
        }
        l0 = l0 * al0 + rs0;
        l1 = l1 * al1 + rs1;

#pragma unroll
        for (int j = 0; j < 8; j++) {
            o[j][0] *= al0; o[j][1] *= al0;
            o[j][2] *= al1; o[j][3] *= al1;
        }

        // ---- O += P V^T ----
        {
            unsigned V = sV[ic & 1];
#pragma unroll
            for (int kk = 0; kk < 4; kk++) {
                unsigned a[4] = {p2[2 * kk][0], p2[2 * kk][1],
                                 p2[2 * kk + 1][0], p2[2 * kk + 1][1]};
#pragma unroll
                for (int i = 0; i < 4; i++) {
                    unsigned r[4];
                    ldsm4(r, V + (unsigned)(i * 16 * FPAD + kk * 16) * 2);
                    unsigned blo[2] = {r[0], r[1]}, bhi[2] = {r[2], r[3]};
                    mma_f16(o[2 * i], a, blo);
                    mma_f16(o[2 * i + 1], a, bhi);
                }
            }
        }

        __syncthreads();   // all warps done reading K[ic] slot & V[ic] slot

        // ---- stage K[ic+3] -> slot ic%3, V[ic+2] -> slot ic%2; always commit ----
        if (ic + 3 < 16) {
            __half* Kn = Kb[ic % 3];
#pragma unroll
            for (int i = 0; i < 4; i++) {
                int rw = sr + i * 16;
                cp16h(&Kn[rw * FPAD + sc], kbase + (size_t)((ic + 3) * 64 + rw) * CHH + sc);
            }
        }
        if (ic + 2 < 16) {
            __half* Vn = Vb[ic & 1];
#pragma unroll
            for (int i = 0; i < 4; i++) {
                int rw = sr + i * 16;
                cp16h(&Vn[rw * FPAD + sc], vbase + (size_t)rw * LL + (ic + 2) * 64 + sc);
            }
        }
        cp_commit();

        if (ic < 15) {
#pragma unroll
            for (int j = 0; j < 8; j++)
#pragma unroll
                for (int r = 0; r < 4; r++) d[j][r] = dn[j][r];
        }
    }

    // deferred l reduction (quad-wide)
    l0 += __shfl_xor_sync(0xffffffffu, l0, 1);
    l0 += __shfl_xor_sync(0xffffffffu, l0, 2);
    l1 += __shfl_xor_sync(0xffffffffu, l1, 1);
    l1 += __shfl_xor_sync(0xffffffffu, l1, 2);

    // ---- epilogue: A[ch][q] staged in smem, coalesced residual-add ----
    float* AS = (float*)smc;
    float inv0 = 1.f / l0, inv1 = 1.f / l1;
    int qg = warp * 16 + g;
#pragma unroll
    for (int j = 0; j < 8; j++) {
        int ch = j * 8 + 2 * tt;
        AS[ch * AS_ST + qg] = o[j][0] * inv0;
        AS[(ch + 1) * AS_ST + qg] = o[j][1] * inv0;
        AS[ch * AS_ST + qg + 8] = o[j][2] * inv1;
        AS[(ch + 1) * AS_ST + qg + 8] = o[j][3] * inv1;
    }
    __syncthreads();
#pragma unroll
    for (int k = 0; k < 32; k++) {
        int idx = t + k * 128;
        int ch = idx >> 6, q = idx & 63;
        size_t gi = ((size_t)b * CC + head * CHH + ch) * LL + q0 * 64 + q;
        out[gi] = x[gi] + AS[ch * AS_ST + q];
    }
}

// ---------------------------------------------------------------------------
extern "C" void kernel_launch(void* const* d_in, const int* in_sizes, int n_in,
                              void* d_out, int out_size) {
    const float* x = (const float*)d_in[0];
    const float* gn_w = (const float*)d_in[1];
    const float* gn_b = (const float*)d_in[2];
    const float* conv_w = (const float*)d_in[3];
    const float* conv_b = (const float*)d_in[4];
    float* out = (float*)d_out;

    wconv_kernel<<<3 * CC * CC / 512, 256>>>(conv_w);
    gn_kernel<<<BB * GG, 256>>>(x, gn_w, gn_b);

    cudaFuncSetAttribute(qkv_gemm, cudaFuncAttributeMaxDynamicSharedMemorySize,
                         GSMEM);
    qkv_gemm<<<1536, 256, GSMEM>>>(conv_b);

    cudaFuncSetAttribute(attn_flash, cudaFuncAttributeMaxDynamicSharedMemorySize,
                         FSMEM);
    dim3 attn_grid(LL / 64, BB * HEADS);
    attn_flash<<<attn_grid, 128, FSMEM>>>(x, out);
}

// round 12
// speedup vs baseline: 1.1092x; 1.1092x over previous
#include <cuda_runtime.h>
#include <cuda_fp16.h>
#include <cstdint>
#include <math.h>

#define BB 16
#define CC 512
#define LL 1024
#define GG 32
#define CPG 16
#define HEADS 8
#define CHH 64

// Scratch (no allocation allowed)
__device__ __half g_hT[BB * LL * CC];                 // h transposed [b][l][c], fp16
__device__ __half g_wh[3 * CC * CC];                  // conv weight fp16
__device__ __half g_qkT[BB * 2 * HEADS * LL * CHH];   // q,k transposed; q pre-scaled by 0.125*log2(e)
__device__ __half g_v[BB * CC * LL];                  // v natural [b][ch_global][l]

__device__ __forceinline__ void mma_f16(float d[4], const unsigned a[4], const unsigned b[2]) {
    asm volatile(
        "mma.sync.aligned.m16n8k16.row.col.f32.f16.f16.f32 "
        "{%0,%1,%2,%3}, {%4,%5,%6,%7}, {%8,%9}, {%0,%1,%2,%3};"
        : "+f"(d[0]), "+f"(d[1]), "+f"(d[2]), "+f"(d[3])
        : "r"(a[0]), "r"(a[1]), "r"(a[2]), "r"(a[3]),
          "r"(b[0]), "r"(b[1]));
}

__device__ __forceinline__ void ldsm4(unsigned r[4], unsigned saddr) {
    asm volatile("ldmatrix.sync.aligned.m8n8.x4.shared.b16 {%0,%1,%2,%3}, [%4];"
                 : "=r"(r[0]), "=r"(r[1]), "=r"(r[2]), "=r"(r[3]) : "r"(saddr));
}

__device__ __forceinline__ unsigned ex2_f16x2(unsigned v) {
    unsigned r;
    asm("ex2.approx.f16x2 %0, %1;" : "=r"(r) : "r"(v));
    return r;
}

__device__ __forceinline__ void cp16h(__half* dst_smem, const __half* src) {
    unsigned d = (unsigned)__cvta_generic_to_shared(dst_smem);
    asm volatile("cp.async.cg.shared.global [%0], [%1], 16;" :: "r"(d), "l"(src));
}
__device__ __forceinline__ void cp_commit() { asm volatile("cp.async.commit_group;"); }
__device__ __forceinline__ void cp_wait1() { asm volatile("cp.async.wait_group 1;"); }

// ---------------------------------------------------------------------------
// Kernel 0: convert conv weight to fp16.
// ---------------------------------------------------------------------------
__global__ void wconv_kernel(const float* __restrict__ W) {
    int i = blockIdx.x * 256 + threadIdx.x;
    float2 w = ((const float2*)W)[i];
    ((__half2*)g_wh)[i] = __floats2half2_rn(w.x, w.y);
}

// ---------------------------------------------------------------------------
// Kernel 1: GroupNorm(32) -> hT [b][l][c] fp16. One block per (b, g).
// ---------------------------------------------------------------------------
__global__ void gn_kernel(const float* __restrict__ x,
                          const float* __restrict__ gw,
                          const float* __restrict__ gb) {
    int bg = blockIdx.x;
    int b = bg >> 5, g = bg & 31;
    const float* xp = x + ((size_t)b * CC + (size_t)g * CPG) * LL;
    const float4* xp4 = (const float4*)xp;
    int t = threadIdx.x;

    float s = 0.f, ss = 0.f;
    for (int i = t; i < CPG * LL / 4; i += 256) {
        float4 v = xp4[i];
        s += v.x + v.y + v.z + v.w;
        ss += v.x * v.x + v.y * v.y + v.z * v.z + v.w * v.w;
    }
    __shared__ float r0[256], r1[256];
    r0[t] = s; r1[t] = ss;
    __syncthreads();
    for (int o = 128; o > 0; o >>= 1) {
        if (t < o) { r0[t] += r0[t + o]; r1[t] += r1[t + o]; }
        __syncthreads();
    }
    const float invN = 1.f / (CPG * LL);
    float mean = r0[0] * invN;
    float var = r1[0] * invN - mean * mean;
    float rstd = rsqrtf(var + 1e-5f);

    int h = t & 1;
    float wv[8], bv[8];
#pragma unroll
    for (int j = 0; j < 8; j++) {
        int cg = g * CPG + h * 8 + j;
        wv[j] = gw[cg] * rstd;
        bv[j] = gb[cg] - mean * wv[j];
    }

    for (int u = t; u < 2 * LL; u += 256) {
        int l = u >> 1;
        uint4 pack;
        __half2* ph = (__half2*)&pack;
#pragma unroll
        for (int j = 0; j < 4; j++) {
            float v0 = xp[(size_t)(h * 8 + 2 * j) * LL + l];
            float v1 = xp[(size_t)(h * 8 + 2 * j + 1) * LL + l];
            ph[j] = __floats2half2_rn(v0 * wv[2 * j] + bv[2 * j],
                                      v1 * wv[2 * j + 1] + bv[2 * j + 1]);
        }
        *(uint4*)(g_hT + ((size_t)b * LL + l) * CC + g * CPG + h * 8) = pack;
    }
}

// ---------------------------------------------------------------------------
// Kernel 2: unified QKV GEMM, 128x128 tiles, K-chunk 64, 3-stage ring,
// ONE sync per K-iteration (write slot's last reader fenced by top sync).
// ---------------------------------------------------------------------------
#define GP 72
#define GTILE (128 * GP)
#define GSMEM (6 * GTILE * 2)

__global__ void __launch_bounds__(256, 2) qkv_gemm(const float* __restrict__ bias) {
    extern __shared__ __half dyn[];
    __half* As[3] = {dyn, dyn + GTILE, dyn + 2 * GTILE};
    __half* Bs[3] = {dyn + 3 * GTILE, dyn + 4 * GTILE, dyn + 5 * GTILE};

    int id = blockIdx.x;
    bool isqk = id < 1024;
    int b, o0, l0;
    const __half *Asrc, *Bsrc;
    if (isqk) {
        int r = id & 63;
        b = id >> 6;
        l0 = (r & 7) * 128; o0 = (r >> 3) * 128;
        Asrc = g_hT + ((size_t)b * LL + l0) * CC;
        Bsrc = g_wh + (size_t)o0 * CC;
    } else {
        int id2 = id - 1024;
        int r = id2 & 31;
        b = id2 >> 5;
        l0 = (r & 7) * 128; o0 = (r >> 3) * 128;
        Asrc = g_wh + (size_t)(2 * CC + o0) * CC;
        Bsrc = g_hT + ((size_t)b * LL + l0) * CC;
    }
    int t = threadIdx.x, warp = t >> 5, lane = t & 31;
    int g = lane >> 2, tt = lane & 3;
    int wm = warp >> 2, wn = warp & 3;

    int sr = t >> 3, sc = (t & 7) * 8;

    int arow = (lane & 7) + 8 * ((lane >> 3) & 1);
    int acol = 8 * (lane >> 4);
    int brow = (lane & 7) + 8 * ((lane >> 4) & 1);
    int bcol = 8 * ((lane >> 3) & 1);
    unsigned aoff = (unsigned)((wm * 64 + arow) * GP + acol) * 2;
    unsigned boff = (unsigned)((wn * 32 + brow) * GP + bcol) * 2;
    unsigned sA[3], sB[3];
#pragma unroll
    for (int i = 0; i < 3; i++) {
        sA[i] = (unsigned)__cvta_generic_to_shared(As[i]) + aoff;
        sB[i] = (unsigned)__cvta_generic_to_shared(Bs[i]) + boff;
    }

    float acc[4][4][4];
#pragma unroll
    for (int m = 0; m < 4; m++)
#pragma unroll
        for (int n = 0; n < 4; n++)
#pragma unroll
            for (int r = 0; r < 4; r++) acc[m][n][r] = 0.f;

    // prologue: chunks 0 and 1, separate groups
#pragma unroll
    for (int i = 0; i < 4; i++) {
        int rw = sr + i * 32;
        cp16h(&As[0][rw * GP + sc], Asrc + (size_t)rw * CC + sc);
        cp16h(&Bs[0][rw * GP + sc], Bsrc + (size_t)rw * CC + sc);
    }
    cp_commit();
#pragma unroll
    for (int i = 0; i < 4; i++) {
        int rw = sr + i * 32;
        cp16h(&As[1][rw * GP + sc], Asrc + (size_t)rw * CC + 64 + sc);
        cp16h(&Bs[1][rw * GP + sc], Bsrc + (size_t)rw * CC + 64 + sc);
    }
    cp_commit();

    int kcur = 0, kst = 2;
    for (int ic = 0; ic < 8; ic++) {
        cp_wait1();
        __syncthreads();

#pragma unroll
        for (int kk = 0; kk < 4; kk++) {
            unsigned a[4][4], bb[2][4];
#pragma unroll
            for (int mm = 0; mm < 4; mm++)
                ldsm4(a[mm], sA[kcur] + (unsigned)(mm * 16 * GP + kk * 16) * 2);
#pragma unroll
            for (int i = 0; i < 2; i++)
                ldsm4(bb[i], sB[kcur] + (unsigned)(i * 16 * GP + kk * 16) * 2);
#pragma unroll
            for (int mm = 0; mm < 4; mm++)
#pragma unroll
                for (int nn = 0; nn < 4; nn++) {
                    unsigned bf[2] = {bb[nn >> 1][2 * (nn & 1)],
                                      bb[nn >> 1][2 * (nn & 1) + 1]};
                    mma_f16(acc[mm][nn], a[mm], bf);
                }
        }

        // stage chunk ic+2 into slot kst (last read iter ic-1; fenced by top sync)
        if (ic + 2 < 8) {
            int c0 = (ic + 2) * 64;
#pragma unroll
            for (int i = 0; i < 4; i++) {
                int rw = sr + i * 32;
                cp16h(&As[kst][rw * GP + sc], Asrc + (size_t)rw * CC + c0 + sc);
                cp16h(&Bs[kst][rw * GP + sc], Bsrc + (size_t)rw * CC + c0 + sc);
            }
        }
        cp_commit();

        kcur = (kcur + 1 == 3) ? 0 : kcur + 1;
        kst = (kst + 1 == 3) ? 0 : kst + 1;
    }

    const float QSC = 0.125f * 1.4426950408889634f;
    if (isqk) {
#pragma unroll
        for (int mm = 0; mm < 4; mm++) {
            int l = l0 + wm * 64 + mm * 16 + g;
#pragma unroll
            for (int nn = 0; nn < 4; nn++) {
                int o = o0 + wn * 32 + nn * 8 + 2 * tt;
                int sec = o >> 9, head = (o >> 6) & 7, ch = o & 63;
                float sc2 = (sec == 0) ? QSC : 1.f;
                __half* dst = g_qkT + (((size_t)b * 2 + sec) * 8 + head) * LL * CHH;
                float2 b2 = *(const float2*)&bias[o];
                *(__half2*)&dst[(size_t)l * CHH + ch] =
                    __floats2half2_rn((acc[mm][nn][0] + b2.x) * sc2, (acc[mm][nn][1] + b2.y) * sc2);
                *(__half2*)&dst[(size_t)(l + 8) * CHH + ch] =
                    __floats2half2_rn((acc[mm][nn][2] + b2.x) * sc2, (acc[mm][nn][3] + b2.y) * sc2);
            }
        }
    } else {
        __half* dst = g_v + (size_t)b * CC * LL;
#pragma unroll
        for (int mm = 0; mm < 4; mm++) {
            int o = o0 + wm * 64 + mm * 16 + g;
            float b0 = bias[2 * CC + o], b1 = bias[2 * CC + o + 8];
#pragma unroll
            for (int nn = 0; nn < 4; nn++) {
                int l = l0 + wn * 32 + nn * 8 + 2 * tt;
                *(__half2*)&dst[(size_t)o * LL + l] =
                    __floats2half2_rn(acc[mm][nn][0] + b0, acc[mm][nn][1] + b0);
                *(__half2*)&dst[(size_t)(o + 8) * LL + l] =
                    __floats2half2_rn(acc[mm][nn][2] + b1, acc[mm][nn][3] + b1);
            }
        }
    }
}

// ---------------------------------------------------------------------------
// Kernel 3: flash attention (R10 structure), 3-slot K/V rings, ONE sync per
// chunk. Dead Q tile recycled as third V slot to keep 4 CTAs/SM.
// ---------------------------------------------------------------------------
#define FPAD 72
#define TILE_B (64 * FPAD * 2)
#define FSMEM (6 * TILE_B)          // Q(=V2) + K0..K2 + V0,V1
#define AS_ST 68

__global__ void __launch_bounds__(128, 4) attn_flash(const float* __restrict__ x,
                                                     float* __restrict__ out) {
    extern __shared__ char smc[];
    __half* Qs = (__half*)smc;                       // tile 0 (later: V slot 2)
    __half* Kb[3] = {(__half*)(smc + TILE_B), (__half*)(smc + 2 * TILE_B),
                     (__half*)(smc + 3 * TILE_B)};
    __half* Vb[3] = {(__half*)(smc + 4 * TILE_B), (__half*)(smc + 5 * TILE_B),
                     (__half*)smc};

    int q0 = blockIdx.x;                 // 0..15 (64 queries each)
    int bh = blockIdx.y;                 // 0..127
    int b = bh >> 3, head = bh & 7;
    int t = threadIdx.x, warp = t >> 5, lane = t & 31;
    int g = lane >> 2, tt = lane & 3;

    const __half* qbase = g_qkT + (((size_t)b * 2 + 0) * 8 + head) * LL * CHH;
    const __half* kbase = g_qkT + (((size_t)b * 2 + 1) * 8 + head) * LL * CHH;
    const __half* vbase = g_v + ((size_t)b * CC + head * CHH) * LL;

    int sr = t >> 3, sc = (t & 7) * 8;

    int brow = (lane & 7) + 8 * ((lane >> 4) & 1);
    int bcol = 8 * ((lane >> 3) & 1);
    unsigned kvoff = (unsigned)(brow * FPAD + bcol) * 2;
    unsigned sK[3], sV[3];
#pragma unroll
    for (int i = 0; i < 3; i++) {
        sK[i] = (unsigned)__cvta_generic_to_shared(Kb[i]) + kvoff;
        sV[i] = (unsigned)__cvta_generic_to_shared(Vb[i]) + kvoff;
    }

    // prologue: g0 = {Q, K0, V0}; g1 = {K1, V1}
#pragma unroll
    for (int i = 0; i < 4; i++) {
        int rw = sr + i * 16;
        cp16h(&Qs[rw * FPAD + sc], qbase + (size_t)(q0 * 64 + rw) * CHH + sc);
        cp16h(&Kb[0][rw * FPAD + sc], kbase + (size_t)rw * CHH + sc);
        cp16h(&Vb[0][rw * FPAD + sc], vbase + (size_t)rw * LL + sc);
    }
    cp_commit();
#pragma unroll
    for (int i = 0; i < 4; i++) {
        int rw = sr + i * 16;
        cp16h(&Kb[1][rw * FPAD + sc], kbase + (size_t)(64 + rw) * CHH + sc);
        cp16h(&Vb[1][rw * FPAD + sc], vbase + (size_t)rw * LL + 64 + sc);
    }
    cp_commit();

    float m0 = -INFINITY, m1 = -INFINITY;
    float l0 = 0.f, l1 = 0.f;
    float o[8][4];
#pragma unroll
    for (int j = 0; j < 8; j++)
#pragma unroll
        for (int r = 0; r < 4; r++) o[j][r] = 0.f;

    // pre-loop: g0 done -> load Q fragments (Qs tile is reused as V slot 2
    // starting at iter0's staging; iter0's top sync fences all qa loads)
    cp_wait1();
    __syncthreads();
    unsigned qa[4][4];
    {
        const __half* qp = &Qs[(warp * 16 + g) * FPAD];
#pragma unroll
        for (int kk = 0; kk < 4; kk++) {
            const __half* p = qp + kk * 16 + 2 * tt;
            qa[kk][0] = *(const unsigned*)p;
            qa[kk][1] = *(const unsigned*)(p + 8 * FPAD);
            qa[kk][2] = *(const unsigned*)(p + 8);
            qa[kk][3] = *(const unsigned*)(p + 8 * FPAD + 8);
        }
    }

    int kcur = 0, kst = 2;
    for (int ic = 0; ic < 16; ic++) {
        cp_wait1();
        __syncthreads();

        unsigned K = sK[kcur], V = sV[kcur];

        // ---- S = Q K^T (log2 domain via q pre-scale) ----
        float d[8][4];
#pragma unroll
        for (int j = 0; j < 8; j++)
            d[j][0] = d[j][1] = d[j][2] = d[j][3] = 0.f;
#pragma unroll
        for (int kk = 0; kk < 4; kk++)
#pragma unroll
            for (int i = 0; i < 4; i++) {
                unsigned r[4];
                ldsm4(r, K + (unsigned)(i * 16 * FPAD + kk * 16) * 2);
                unsigned blo[2] = {r[0], r[1]}, bhi[2] = {r[2], r[3]};
                mma_f16(d[2 * i], qa[kk], blo);
                mma_f16(d[2 * i + 1], qa[kk], bhi);
            }

        // ---- online softmax (exp2 domain, f16x2 MUFU) ----
        float cm0 = -INFINITY, cm1 = -INFINITY;
#pragma unroll
        for (int j = 0; j < 8; j++) {
            cm0 = fmaxf(cm0, fmaxf(d[j][0], d[j][1]));
            cm1 = fmaxf(cm1, fmaxf(d[j][2], d[j][3]));
        }
        cm0 = fmaxf(cm0, __shfl_xor_sync(0xffffffffu, cm0, 1));
        cm0 = fmaxf(cm0, __shfl_xor_sync(0xffffffffu, cm0, 2));
        cm1 = fmaxf(cm1, __shfl_xor_sync(0xffffffffu, cm1, 1));
        cm1 = fmaxf(cm1, __shfl_xor_sync(0xffffffffu, cm1, 2));

        float mn0 = fmaxf(m0, cm0), mn1 = fmaxf(m1, cm1);
        float al0 = exp2f(m0 - mn0), al1 = exp2f(m1 - mn1);
        m0 = mn0; m1 = mn1;

        float rs0 = 0.f, rs1 = 0.f;
        unsigned p2[8][2];
#pragma unroll
        for (int j = 0; j < 8; j++) {
            __half2 s01 = __floats2half2_rn(d[j][0] - m0, d[j][1] - m0);
            __half2 s23 = __floats2half2_rn(d[j][2] - m1, d[j][3] - m1);
            p2[j][0] = ex2_f16x2(*(unsigned*)&s01);
            p2[j][1] = ex2_f16x2(*(unsigned*)&s23);
            float2 f01 = __half22float2(*(__half2*)&p2[j][0]);
            float2 f23 = __half22float2(*(__half2*)&p2[j][1]);
            rs0 += f01.x + f01.y;
            rs1 += f23.x + f23.y;
        }
        l0 = l0 * al0 + rs0;
        l1 = l1 * al1 + rs1;

#pragma unroll
        for (int j = 0; j < 8; j++) {
            o[j][0] *= al0; o[j][1] *= al0;
            o[j][2] *= al1; o[j][3] *= al1;
        }

        // ---- O += P V^T ----
#pragma unroll
        for (int kk = 0; kk < 4; kk++) {
            unsigned a[4] = {p2[2 * kk][0], p2[2 * kk][1],
                             p2[2 * kk + 1][0], p2[2 * kk + 1][1]};
#pragma unroll
            for (int i = 0; i < 4; i++) {
                unsigned r[4];
                ldsm4(r, V + (unsigned)(i * 16 * FPAD + kk * 16) * 2);
                unsigned blo[2] = {r[0], r[1]}, bhi[2] = {r[2], r[3]};
                mma_f16(o[2 * i], a, blo);
                mma_f16(o[2 * i + 1], a, bhi);
            }
        }

        // ---- stage chunk ic+2 into slot kst (last read iter ic-1) ----
        if (ic + 2 < 16) {
            __half* Kn = Kb[kst];
            __half* Vn = Vb[kst];
            int s0 = (ic + 2) * 64;
#pragma unroll
            for (int i = 0; i < 4; i++) {
                int rw = sr + i * 16;
                cp16h(&Kn[rw * FPAD + sc], kbase + (size_t)(s0 + rw) * CHH + sc);
                cp16h(&Vn[rw * FPAD + sc], vbase + (size_t)rw * LL + s0 + sc);
            }
        }
        cp_commit();

        kcur = (kcur + 1 == 3) ? 0 : kcur + 1;
        kst = (kst + 1 == 3) ? 0 : kst + 1;
    }

    // deferred l reduction (quad-wide)
    l0 += __shfl_xor_sync(0xffffffffu, l0, 1);
    l0 += __shfl_xor_sync(0xffffffffu, l0, 2);
    l1 += __shfl_xor_sync(0xffffffffu, l1, 1);
    l1 += __shfl_xor_sync(0xffffffffu, l1, 2);

    __syncthreads();   // AS overlaps tiles 0-1; fence iter-15 K/V readers

    // ---- epilogue: A[ch][q] staged in smem, coalesced residual-add ----
    float* AS = (float*)smc;
    float inv0 = 1.f / l0, inv1 = 1.f / l1;
    int qg = warp * 16 + g;
#pragma unroll
    for (int j = 0; j < 8; j++) {
        int ch = j * 8 + 2 * tt;
        AS[ch * AS_ST + qg] = o[j][0] * inv0;
        AS[(ch + 1) * AS_ST + qg] = o[j][1] * inv0;
        AS[ch * AS_ST + qg + 8] = o[j][2] * inv1;
        AS[(ch + 1) * AS_ST + qg + 8] = o[j][3] * inv1;
    }
    __syncthreads();
#pragma unroll
    for (int k = 0; k < 32; k++) {
        int idx = t + k * 128;
        int ch = idx >> 6, q = idx & 63;
        size_t gi = ((size_t)b * CC + head * CHH + ch) * LL + q0 * 64 + q;
        out[gi] = x[gi] + AS[ch * AS_ST + q];
    }
}

// ---------------------------------------------------------------------------
extern "C" void kernel_launch(void* const* d_in, const int* in_sizes, int n_in,
                              void* d_out, int out_size) {
    const float* x = (const float*)d_in[0];
    const float* gn_w = (const float*)d_in[1];
    const float* gn_b = (const float*)d_in[2];
    const float* conv_w = (const float*)d_in[3];
    const float* conv_b = (const float*)d_in[4];
    float* out = (float*)d_out;

    wconv_kernel<<<3 * CC * CC / 512, 256>>>(conv_w);
    gn_kernel<<<BB * GG, 256>>>(x, gn_w, gn_b);

    cudaFuncSetAttribute(qkv_gemm, cudaFuncAttributeMaxDynamicSharedMemorySize,
                         GSMEM);
    qkv_gemm<<<1536, 256, GSMEM>>>(conv_b);

    cudaFuncSetAttribute(attn_flash, cudaFuncAttributeMaxDynamicSharedMemorySize,
                         FSMEM);
    dim3 attn_grid(LL / 64, BB * HEADS);
    attn_flash<<<attn_grid, 128, FSMEM>>>(x, out);
}